// round 12
// baseline (speedup 1.0000x reference)
#include <cuda_runtime.h>
#include <cstddef>

// ---------------------------------------------------------------------------
// ContextNet (RIFE-style) on GB300 — padded buffers, scalar-FFMA conv,
// conv_a: 8co x 4rows, conv_b: fused splat (MINB=3). Dual batch pipeline
// (R10-proven 3-stream graph), scr-zeroing folded into norm_transpose.
// Levels: (Cin,Cout,Hin): (3,16,512) (16,32,256) (32,64,128) (64,128,64)
// ---------------------------------------------------------------------------

#define NB 16   // total batch
#define NBH 8   // per-pipeline half

__device__ float g_fa[33000000];                       // conv_a outputs (padded)
__device__ float g_fb[33000000];                       // conv_b outputs (padded)
__device__ float g_scrA[(size_t)16 * 16 * 256 * 256];  // channel-last splat scratch (ping)
__device__ float g_scrB[(size_t)16 * 16 * 256 * 256];  // (pong)
__device__ float g_cntA[(size_t)16 * 256 * 256];
__device__ float g_cntB[(size_t)16 * 256 * 256];
__device__ float g_fl[3000000];                        // all 4 halved flows

// ---- vectorized global reduction (fp32 x4) --------------------------------
__device__ __forceinline__ void red_add_v4(float* p, float a, float b,
                                           float c, float d) {
    asm volatile("red.global.add.v4.f32 [%0], {%1, %2, %3, %4};"
                 :: "l"(p), "f"(a), "f"(b), "f"(c), "f"(d) : "memory");
}

// ---------------------------------------------------------------------------
// Merged border zeroing: blockIdx.y selects one of up to 8 jobs.
// ---------------------------------------------------------------------------
struct BorderJobs {
    int    sel[8];    // 0 = fa, 1 = fb
    long long off[8];
    int    NC[8];
    int    H[8];
    int    njobs;
};

__global__ void zero_borders_all(float* __restrict__ fa, float* __restrict__ fb,
                                 BorderJobs J) {
    int j = blockIdx.y;
    if (j >= J.njobs) return;
    int H = J.H[j], NC = J.NC[j];
    int W = H;
    int per = 2 * (W + 2) + 2 * H;
    int idx = blockIdx.x * blockDim.x + threadIdx.x;
    if (idx >= NC * per) return;
    int c = idx / per, r = idx % per;
    float* p = (J.sel[j] ? fb : fa) + J.off[j] + (size_t)c * (H + 2) * (W + 2);
    if (r < W + 2) {
        p[r] = 0.f;
    } else if (r < 2 * (W + 2)) {
        p[(size_t)(H + 1) * (W + 2) + (r - (W + 2))] = 0.f;
    } else {
        int rr = r - 2 * (W + 2);
        int y = rr % H;
        bool right = rr >= H;
        p[(size_t)(y + 1) * (W + 2) + (right ? (W + 1) : 0)] = 0.f;
    }
}

// ---------------------------------------------------------------------------
// 3x3 conv + bias + PReLU; COB output channels x ROWS rows per thread.
// n0: batch offset. Optional fused splat (COB==4) and optional writeout.
// ---------------------------------------------------------------------------
template <int STRIDE, int ROWS, int COB, bool PRED, bool SPLAT, bool WROUT, int MINB>
__global__ void __launch_bounds__(256, MINB)
conv3x3_prelu(const float* __restrict__ in,
              const float* __restrict__ wt,
              const float* __restrict__ bias,
              const float* __restrict__ alpha,
              float* __restrict__ out,
              int Cin, int Cout, int Hin, int Win,
              int inPitch, size_t inPlane,
              int outPitch, size_t outPlane,
              const float* __restrict__ flw,
              float* __restrict__ scr,
              float* __restrict__ cnt,
              int n0) {
    const int cg = Cout / COB;
    const int co0 = (blockIdx.z % cg) * COB;
    const int n   = n0 + blockIdx.z / cg;

    extern __shared__ float sw[];            // [COB][Cin][9]
    const int tid = threadIdx.y * 32 + threadIdx.x;
    const int nw = COB * Cin * 9;
    const float* wsrc = wt + (size_t)co0 * Cin * 9;
    for (int i = tid; i < nw; i += 256) sw[i] = wsrc[i];
    __syncthreads();

    const int x  = blockIdx.x * 32 + threadIdx.x;
    const int y0 = blockIdx.y * (8 * ROWS) + threadIdx.y * ROWS;

    float acc[COB][ROWS];
#pragma unroll
    for (int c = 0; c < COB; c++)
#pragma unroll
        for (int j = 0; j < ROWS; j++) acc[c][j] = 0.f;

    const float* ib = in + (size_t)n * Cin * inPlane;
    constexpr int NR = (STRIDE == 1) ? (ROWS + 2) : (2 * ROWS + 1);

    for (int ci = 0; ci < Cin; ci++) {
        const float* ip = ib + (size_t)ci * inPlane;
        float v[NR][3];
#pragma unroll
        for (int r = 0; r < NR; r++) {
            const int iy = STRIDE * y0 - 1 + r;
            const float* rp = ip + (ptrdiff_t)iy * inPitch + (STRIDE * x - 1);
            if (PRED) {
                bool yok = ((unsigned)iy < (unsigned)Hin);
#pragma unroll
                for (int c = 0; c < 3; c++) {
                    int ix = STRIDE * x - 1 + c;
                    v[r][c] = (yok && (unsigned)ix < (unsigned)Win) ? rp[c] : 0.f;
                }
            } else {
#pragma unroll
                for (int c = 0; c < 3; c++) v[r][c] = rp[c];
            }
        }
#pragma unroll
        for (int c4 = 0; c4 < COB; c4++) {
            const float* w9 = sw + (c4 * Cin + ci) * 9;
            float w[9];
#pragma unroll
            for (int k = 0; k < 9; k++) w[k] = w9[k];
#pragma unroll
            for (int j = 0; j < ROWS; j++)
#pragma unroll
                for (int ky = 0; ky < 3; ky++)
#pragma unroll
                    for (int kx = 0; kx < 3; kx++)
                        acc[c4][j] = fmaf(v[STRIDE * j + ky][kx], w[ky * 3 + kx], acc[c4][j]);
        }
    }

    // bias + PReLU in place
#pragma unroll
    for (int c4 = 0; c4 < COB; c4++) {
        const int co = co0 + c4;
        const float bv = bias[co];
        const float av = alpha[co];
#pragma unroll
        for (int j = 0; j < ROWS; j++) {
            float o = acc[c4][j] + bv;
            acc[c4][j] = (o >= 0.f) ? o : av * o;
        }
    }

    if (WROUT) {
#pragma unroll
        for (int c4 = 0; c4 < COB; c4++) {
            float* ob = out + (size_t)(n * Cout + co0 + c4) * outPlane;
#pragma unroll
            for (int j = 0; j < ROWS; j++)
                ob[(size_t)(y0 + j) * outPitch + x] = acc[c4][j];
        }
    }

    if (SPLAT) {                             // requires COB == 4
        const int W = Win / STRIDE;          // == Hout == Wout
        const int HW = W * W;
        const float* fp = flw + (size_t)n * 2 * HW;
        float* sb = scr + (size_t)n * HW * Cout + co0;
#pragma unroll
        for (int j = 0; j < ROWS; j++) {
            const int yy = y0 + j;
            const int p = yy * W + x;
            float fx = fp[p] + (float)x;
            float fy = fp[HW + p] + (float)yy;
            float x0f = floorf(fx), y0f = floorf(fy);
            int ix0 = (int)x0f, iy0 = (int)y0f;
            float wx1 = fx - x0f, wy1 = fy - y0f;
            float wx0 = 1.f - wx1, wy0 = 1.f - wy1;
            int   xi[4] = {ix0, ix0 + 1, ix0,     ix0 + 1};
            int   yi[4] = {iy0, iy0,     iy0 + 1, iy0 + 1};
            float wv[4] = {wx0 * wy0, wx1 * wy0, wx0 * wy1, wx1 * wy1};
            float s0 = acc[0][j], s1 = acc[1][j], s2 = acc[2][j], s3 = acc[3][j];
#pragma unroll
            for (int k = 0; k < 4; k++) {
                bool ok = ((unsigned)xi[k] < (unsigned)W) &&
                          ((unsigned)yi[k] < (unsigned)W);
                if (ok) {
                    int tgt = yi[k] * W + xi[k];
                    float w = wv[k];
                    red_add_v4(sb + (size_t)tgt * Cout,
                               s0 * w, s1 * w, s2 * w, s3 * w);
                    if (co0 == 0)
                        atomicAdd(&cnt[(size_t)n * HW + tgt], w);
                }
            }
        }
    }
}

// ---------------------------------------------------------------------------
// Flow halving: 2x2 mean * 0.5 == sum * 0.125
// ---------------------------------------------------------------------------
__global__ void halve_flow_kernel(const float* __restrict__ in,
                                  float* __restrict__ out, int Hout, int Wout) {
    int idx = blockIdx.x * blockDim.x + threadIdx.x;
    int total = NB * 2 * Hout * Wout;
    if (idx >= total) return;
    int w = idx % Wout;
    int h = (idx / Wout) % Hout;
    int nc = idx / (Wout * Hout);
    int Win = 2 * Wout;
    const float* ip = in + (size_t)nc * (4 * Hout * Wout);
    const float* r0 = ip + (2 * h) * Win + 2 * w;
    const float* r1 = r0 + Win;
    out[idx] = (r0[0] + r0[1] + r1[0] + r1[1]) * 0.125f;
}

// ---------------------------------------------------------------------------
// Transpose channel-last scratch [n][p][c] -> NCHW out, dividing by count.
// ZEROES scr behind itself (each element read by exactly one block), so the
// ping-pong reuse at level L+2 needs no separate memset.
// ---------------------------------------------------------------------------
__global__ void norm_transpose(float* __restrict__ scr,
                               const float* __restrict__ cnt,
                               float* __restrict__ out,
                               int C, int HW) {
    __shared__ float tile[32][33];
    const int n  = blockIdx.z;
    const int p0 = blockIdx.x * 32;
    const int c0 = blockIdx.y * 32;
    const int tx = threadIdx.x, ty = threadIdx.y;

    float* sb = scr + (size_t)n * HW * C;
    const int c = c0 + tx;
#pragma unroll
    for (int r = 0; r < 4; r++) {
        int pl = ty + 8 * r;
        if (c < C) {
            size_t idx = (size_t)(p0 + pl) * C + c;
            tile[pl][tx] = sb[idx];
            sb[idx] = 0.f;                 // re-zero for next reuse
        }
    }
    __syncthreads();

    float cv = cnt[(size_t)n * HW + p0 + tx];
    float inv = 1.f / ((cv == 0.f) ? 1.f : cv);
#pragma unroll
    for (int r = 0; r < 4; r++) {
        int cc = c0 + ty + 8 * r;
        if (cc < C)
            out[((size_t)n * C + cc) * HW + p0 + tx] = tile[tx][ty + 8 * r] * inv;
    }
}

// ---------------------------------------------------------------------------
// Host launcher — dual batch pipeline + side stream (graph-capturable).
// ---------------------------------------------------------------------------
extern "C" void kernel_launch(void* const* d_in, const int* in_sizes, int n_in,
                              void* d_out, int out_size) {
    const float* img  = (const float*)d_in[0];
    const float* flow = (const float*)d_in[1];
    float* out = (float*)d_out;

    static cudaStream_t s2 = nullptr, s3 = nullptr;
    static cudaEvent_t evFork, evJoin, evPre[4], evB0[4], evB1[4];
    if (!s2) {
        cudaStreamCreateWithFlags(&s2, cudaStreamNonBlocking);
        cudaStreamCreateWithFlags(&s3, cudaStreamNonBlocking);
        cudaEventCreateWithFlags(&evFork, cudaEventDisableTiming);
        cudaEventCreateWithFlags(&evJoin, cudaEventDisableTiming);
        for (int i = 0; i < 4; i++) {
            cudaEventCreateWithFlags(&evPre[i], cudaEventDisableTiming);
            cudaEventCreateWithFlags(&evB0[i], cudaEventDisableTiming);
            cudaEventCreateWithFlags(&evB1[i], cudaEventDisableTiming);
        }
    }

    float *fa, *fb, *scrA, *scrB, *cntA, *cntB, *flbuf;
    cudaGetSymbolAddress((void**)&fa,   g_fa);
    cudaGetSymbolAddress((void**)&fb,   g_fb);
    cudaGetSymbolAddress((void**)&scrA, g_scrA);
    cudaGetSymbolAddress((void**)&scrB, g_scrB);
    cudaGetSymbolAddress((void**)&cntA, g_cntA);
    cudaGetSymbolAddress((void**)&cntB, g_cntB);
    cudaGetSymbolAddress((void**)&flbuf, g_fl);

    const int Cin[4]  = {3, 16, 32, 64};
    const int Cout[4] = {16, 32, 64, 128};
    const int Hin[4]  = {512, 256, 128, 64};

    size_t regOff[4];
    float* fl[4];
    {
        size_t a = 0, f = 0;
        for (int L = 0; L < 4; L++) {
            regOff[L] = a;
            int ho = Hin[L] / 2;
            a += (size_t)NB * Cout[L] * (ho + 2) * (ho + 2);
            fl[L] = flbuf + f;
            f += (size_t)NB * 2 * ho * ho;
        }
    }
    float* scrP[4] = {scrA, scrB, scrA, scrB};
    float* cntP[4] = {cntA, cntB, cntA, cntB};

    // ---- fork ----
    cudaEventRecord(evFork, 0);
    cudaStreamWaitEvent(s2, evFork, 0);
    cudaStreamWaitEvent(s3, evFork, 0);

    // ---- side stream: borders (merged), flow chain, first memsets ----
    {
        BorderJobs J{};
        int nj = 0;
        int maxtot = 0;
        for (int L = 0; L < 4; L++) {
            int ho = Hin[L] / 2;
            J.sel[nj] = 0; J.off[nj] = (long long)regOff[L];
            J.NC[nj] = NB * Cout[L]; J.H[nj] = ho;
            int tot = J.NC[nj] * (2 * (ho + 2) + 2 * ho);
            if (tot > maxtot) maxtot = tot;
            nj++;
            if (L < 3) {
                J.sel[nj] = 1; J.off[nj] = (long long)regOff[L];
                J.NC[nj] = NB * Cout[L]; J.H[nj] = ho;
                nj++;
            }
        }
        J.njobs = nj;
        dim3 grd((maxtot + 255) / 256, nj);
        zero_borders_all<<<grd, 256, 0, s2>>>(fa, fb, J);
    }

    {
        int ho0 = Hin[0] / 2;
        halve_flow_kernel<<<(NB * 2 * ho0 * ho0 + 255) / 256, 256, 0, s2>>>(
            flow, fl[0], ho0, ho0);
        cudaMemsetAsync(scrP[0], 0, (size_t)NB * Cout[0] * ho0 * ho0 * sizeof(float), s2);
        cudaMemsetAsync(cntP[0], 0, (size_t)NB * ho0 * ho0 * sizeof(float), s2);
        cudaEventRecord(evPre[0], s2);

        for (int L = 1; L < 4; L++) {
            int ho = Hin[L] / 2;
            halve_flow_kernel<<<(NB * 2 * ho * ho + 255) / 256, 256, 0, s2>>>(
                fl[L - 1], fl[L], ho, ho);
        }
        int ho1 = Hin[1] / 2;
        cudaMemsetAsync(scrP[1], 0, (size_t)NB * Cout[1] * ho1 * ho1 * sizeof(float), s2);
        cudaMemsetAsync(cntP[1], 0, (size_t)NB * ho1 * ho1 * sizeof(float), s2);
        cudaEventRecord(evPre[1], s2);
    }

    size_t off = 0;
    size_t outOff[4];
    for (int L = 0; L < 4; L++) { outOff[L] = off; off += (size_t)NB * Cout[L] * (Hin[L] / 2) * (Hin[L] / 2); }

    cudaStream_t hs[2] = {(cudaStream_t)0, s3};
    cudaEvent_t* evBh[2] = {evB0, evB1};

    for (int L = 0; L < 4; L++) {
        const int ci = Cin[L], co = Cout[L], hi = Hin[L], ho = hi / 2;
        const float* wA = (const float*)d_in[2 + 6 * L + 0];
        const float* bA = (const float*)d_in[2 + 6 * L + 1];
        const float* aA = (const float*)d_in[2 + 6 * L + 2];
        const float* wB = (const float*)d_in[2 + 6 * L + 3];
        const float* bB = (const float*)d_in[2 + 6 * L + 4];
        const float* aB = (const float*)d_in[2 + 6 * L + 5];

        const int po = ho + 2;
        const size_t planeO = (size_t)po * po;
        float* faL = fa + regOff[L] + po + 1;
        float* fbL = fb + regOff[L] + po + 1;

        for (int h = 0; h < 2; h++) {
            cudaStream_t st = hs[h];
            const int n0 = h * NBH;

            // --- conv_a: stride 2, 8co x 4rows ---
            {
                dim3 blk(32, 8);
                dim3 grd(ho / 32, ho / 32, NBH * (co / 8));
                size_t sm = 8 * ci * 9 * sizeof(float);
                if (L == 0) {
                    conv3x3_prelu<2, 4, 8, true, false, true, 2><<<grd, blk, sm, st>>>(
                        img, wA, bA, aA, faL, ci, co, hi, hi,
                        hi, (size_t)hi * hi, po, planeO, nullptr, nullptr, nullptr, n0);
                } else {
                    const int pi = hi + 2;
                    const float* inL = fb + regOff[L - 1] + pi + 1;
                    conv3x3_prelu<2, 4, 8, false, false, true, 2><<<grd, blk, sm, st>>>(
                        inL, wA, bA, aA, faL, ci, co, hi, hi,
                        pi, (size_t)pi * pi, po, planeO, nullptr, nullptr, nullptr, n0);
                }
            }

            cudaStreamWaitEvent(st, evPre[L], 0);

            // --- conv_b with fused splat; no fb write at L3 ---
            {
                dim3 blk(32, 8);
                size_t sm = 4 * co * 9 * sizeof(float);
                if (ho >= 64) {
                    dim3 grd(ho / 32, ho / 64, NBH * (co / 4));
                    conv3x3_prelu<1, 8, 4, false, true, true, 3><<<grd, blk, sm, st>>>(
                        faL, wB, bB, aB, fbL, co, co, ho, ho,
                        po, planeO, po, planeO, fl[L], scrP[L], cntP[L], n0);
                } else {
                    dim3 grd(ho / 32, ho / 32, NBH * (co / 4));
                    conv3x3_prelu<1, 4, 4, false, true, false, 3><<<grd, blk, sm, st>>>(
                        faL, wB, bB, aB, fbL, co, co, ho, ho,
                        po, planeO, po, planeO, fl[L], scrP[L], cntP[L], n0);
                }
            }
            cudaEventRecord(evBh[h][L], st);
        }

        // --- side stream: transpose (re-zeroes scr) after BOTH halves; cnt memset for L+2 ---
        cudaStreamWaitEvent(s2, evB0[L], 0);
        cudaStreamWaitEvent(s2, evB1[L], 0);
        {
            int HW = ho * ho;
            dim3 blk(32, 8);
            dim3 grd(HW / 32, (co + 31) / 32, NB);
            norm_transpose<<<grd, blk, 0, s2>>>(scrP[L], cntP[L], out + outOff[L], co, HW);
        }
        if (L + 2 < 4) {
            int ho2 = Hin[L + 2] / 2;
            cudaMemsetAsync(cntP[L + 2], 0,
                            (size_t)NB * ho2 * ho2 * sizeof(float), s2);
            cudaEventRecord(evPre[L + 2], s2);
        }
    }

    // ---- join ----
    cudaEventRecord(evJoin, s2);
    cudaStreamWaitEvent(0, evJoin, 0);
}

// round 13
// speedup vs baseline: 1.5537x; 1.5537x over previous
#include <cuda_runtime.h>
#include <cstddef>

// ---------------------------------------------------------------------------
// ContextNet (RIFE-style) on GB300 — padded buffers, scalar-FFMA conv,
// conv_a: 8co x 4rows, conv_b: fused splat. Batch-split dual pipeline:
// batches 0-7 on stream0, 8-15 on stream s3, prep/transpose on s2.
// (Exact R10 configuration — best proven: 1085.5 us.)
// Levels: (Cin,Cout,Hin): (3,16,512) (16,32,256) (32,64,128) (64,128,64)
// ---------------------------------------------------------------------------

#define NB 16   // total batch
#define NBH 8   // per-pipeline half

__device__ float g_fa[33000000];                       // conv_a outputs (padded)
__device__ float g_fb[33000000];                       // conv_b outputs (padded)
__device__ float g_scrA[(size_t)16 * 16 * 256 * 256];  // channel-last splat scratch (ping)
__device__ float g_scrB[(size_t)16 * 16 * 256 * 256];  // (pong)
__device__ float g_cntA[(size_t)16 * 256 * 256];
__device__ float g_cntB[(size_t)16 * 256 * 256];
__device__ float g_fl[3000000];                        // all 4 halved flows

// ---- vectorized global reduction (fp32 x4) --------------------------------
__device__ __forceinline__ void red_add_v4(float* p, float a, float b,
                                           float c, float d) {
    asm volatile("red.global.add.v4.f32 [%0], {%1, %2, %3, %4};"
                 :: "l"(p), "f"(a), "f"(b), "f"(c), "f"(d) : "memory");
}

// ---------------------------------------------------------------------------
// Merged border zeroing: blockIdx.y selects one of up to 8 jobs.
// ---------------------------------------------------------------------------
struct BorderJobs {
    int    sel[8];    // 0 = fa, 1 = fb
    long long off[8];
    int    NC[8];
    int    H[8];
    int    njobs;
};

__global__ void zero_borders_all(float* __restrict__ fa, float* __restrict__ fb,
                                 BorderJobs J) {
    int j = blockIdx.y;
    if (j >= J.njobs) return;
    int H = J.H[j], NC = J.NC[j];
    int W = H;
    int per = 2 * (W + 2) + 2 * H;
    int idx = blockIdx.x * blockDim.x + threadIdx.x;
    if (idx >= NC * per) return;
    int c = idx / per, r = idx % per;
    float* p = (J.sel[j] ? fb : fa) + J.off[j] + (size_t)c * (H + 2) * (W + 2);
    if (r < W + 2) {
        p[r] = 0.f;
    } else if (r < 2 * (W + 2)) {
        p[(size_t)(H + 1) * (W + 2) + (r - (W + 2))] = 0.f;
    } else {
        int rr = r - 2 * (W + 2);
        int y = rr % H;
        bool right = rr >= H;
        p[(size_t)(y + 1) * (W + 2) + (right ? (W + 1) : 0)] = 0.f;
    }
}

// ---------------------------------------------------------------------------
// 3x3 conv + bias + PReLU; COB output channels x ROWS rows per thread.
// n0: batch offset (dual-pipeline). Optional fused splat (COB==4) and
// optional feature writeout.
// ---------------------------------------------------------------------------
template <int STRIDE, int ROWS, int COB, bool PRED, bool SPLAT, bool WROUT, int MINB>
__global__ void __launch_bounds__(256, MINB)
conv3x3_prelu(const float* __restrict__ in,
              const float* __restrict__ wt,
              const float* __restrict__ bias,
              const float* __restrict__ alpha,
              float* __restrict__ out,
              int Cin, int Cout, int Hin, int Win,
              int inPitch, size_t inPlane,
              int outPitch, size_t outPlane,
              const float* __restrict__ flw,
              float* __restrict__ scr,
              float* __restrict__ cnt,
              int n0) {
    const int cg = Cout / COB;
    const int co0 = (blockIdx.z % cg) * COB;
    const int n   = n0 + blockIdx.z / cg;

    extern __shared__ float sw[];            // [COB][Cin][9]
    const int tid = threadIdx.y * 32 + threadIdx.x;
    const int nw = COB * Cin * 9;
    const float* wsrc = wt + (size_t)co0 * Cin * 9;
    for (int i = tid; i < nw; i += 256) sw[i] = wsrc[i];
    __syncthreads();

    const int x  = blockIdx.x * 32 + threadIdx.x;
    const int y0 = blockIdx.y * (8 * ROWS) + threadIdx.y * ROWS;

    float acc[COB][ROWS];
#pragma unroll
    for (int c = 0; c < COB; c++)
#pragma unroll
        for (int j = 0; j < ROWS; j++) acc[c][j] = 0.f;

    const float* ib = in + (size_t)n * Cin * inPlane;
    constexpr int NR = (STRIDE == 1) ? (ROWS + 2) : (2 * ROWS + 1);

    for (int ci = 0; ci < Cin; ci++) {
        const float* ip = ib + (size_t)ci * inPlane;
        float v[NR][3];
#pragma unroll
        for (int r = 0; r < NR; r++) {
            const int iy = STRIDE * y0 - 1 + r;
            const float* rp = ip + (ptrdiff_t)iy * inPitch + (STRIDE * x - 1);
            if (PRED) {
                bool yok = ((unsigned)iy < (unsigned)Hin);
#pragma unroll
                for (int c = 0; c < 3; c++) {
                    int ix = STRIDE * x - 1 + c;
                    v[r][c] = (yok && (unsigned)ix < (unsigned)Win) ? rp[c] : 0.f;
                }
            } else {
#pragma unroll
                for (int c = 0; c < 3; c++) v[r][c] = rp[c];
            }
        }
#pragma unroll
        for (int c4 = 0; c4 < COB; c4++) {
            const float* w9 = sw + (c4 * Cin + ci) * 9;
            float w[9];
#pragma unroll
            for (int k = 0; k < 9; k++) w[k] = w9[k];
#pragma unroll
            for (int j = 0; j < ROWS; j++)
#pragma unroll
                for (int ky = 0; ky < 3; ky++)
#pragma unroll
                    for (int kx = 0; kx < 3; kx++)
                        acc[c4][j] = fmaf(v[STRIDE * j + ky][kx], w[ky * 3 + kx], acc[c4][j]);
        }
    }

    // bias + PReLU in place
#pragma unroll
    for (int c4 = 0; c4 < COB; c4++) {
        const int co = co0 + c4;
        const float bv = bias[co];
        const float av = alpha[co];
#pragma unroll
        for (int j = 0; j < ROWS; j++) {
            float o = acc[c4][j] + bv;
            acc[c4][j] = (o >= 0.f) ? o : av * o;
        }
    }

    if (WROUT) {
#pragma unroll
        for (int c4 = 0; c4 < COB; c4++) {
            float* ob = out + (size_t)(n * Cout + co0 + c4) * outPlane;
#pragma unroll
            for (int j = 0; j < ROWS; j++)
                ob[(size_t)(y0 + j) * outPitch + x] = acc[c4][j];
        }
    }

    if (SPLAT) {                             // requires COB == 4
        const int W = Win / STRIDE;          // == Hout == Wout
        const int HW = W * W;
        const float* fp = flw + (size_t)n * 2 * HW;
        float* sb = scr + (size_t)n * HW * Cout + co0;
#pragma unroll
        for (int j = 0; j < ROWS; j++) {
            const int yy = y0 + j;
            const int p = yy * W + x;
            float fx = fp[p] + (float)x;
            float fy = fp[HW + p] + (float)yy;
            float x0f = floorf(fx), y0f = floorf(fy);
            int ix0 = (int)x0f, iy0 = (int)y0f;
            float wx1 = fx - x0f, wy1 = fy - y0f;
            float wx0 = 1.f - wx1, wy0 = 1.f - wy1;
            int   xi[4] = {ix0, ix0 + 1, ix0,     ix0 + 1};
            int   yi[4] = {iy0, iy0,     iy0 + 1, iy0 + 1};
            float wv[4] = {wx0 * wy0, wx1 * wy0, wx0 * wy1, wx1 * wy1};
            float s0 = acc[0][j], s1 = acc[1][j], s2 = acc[2][j], s3 = acc[3][j];
#pragma unroll
            for (int k = 0; k < 4; k++) {
                bool ok = ((unsigned)xi[k] < (unsigned)W) &&
                          ((unsigned)yi[k] < (unsigned)W);
                if (ok) {
                    int tgt = yi[k] * W + xi[k];
                    float w = wv[k];
                    red_add_v4(sb + (size_t)tgt * Cout,
                               s0 * w, s1 * w, s2 * w, s3 * w);
                    if (co0 == 0)
                        atomicAdd(&cnt[(size_t)n * HW + tgt], w);
                }
            }
        }
    }
}

// ---------------------------------------------------------------------------
// Flow halving: 2x2 mean * 0.5 == sum * 0.125
// ---------------------------------------------------------------------------
__global__ void halve_flow_kernel(const float* __restrict__ in,
                                  float* __restrict__ out, int Hout, int Wout) {
    int idx = blockIdx.x * blockDim.x + threadIdx.x;
    int total = NB * 2 * Hout * Wout;
    if (idx >= total) return;
    int w = idx % Wout;
    int h = (idx / Wout) % Hout;
    int nc = idx / (Wout * Hout);
    int Win = 2 * Wout;
    const float* ip = in + (size_t)nc * (4 * Hout * Wout);
    const float* r0 = ip + (2 * h) * Win + 2 * w;
    const float* r1 = r0 + Win;
    out[idx] = (r0[0] + r0[1] + r1[0] + r1[1]) * 0.125f;
}

// ---------------------------------------------------------------------------
// Transpose channel-last scratch [n][p][c] -> NCHW out, dividing by count.
// ---------------------------------------------------------------------------
__global__ void norm_transpose(const float* __restrict__ scr,
                               const float* __restrict__ cnt,
                               float* __restrict__ out,
                               int C, int HW) {
    __shared__ float tile[32][33];
    const int n  = blockIdx.z;
    const int p0 = blockIdx.x * 32;
    const int c0 = blockIdx.y * 32;
    const int tx = threadIdx.x, ty = threadIdx.y;

    const float* sb = scr + (size_t)n * HW * C;
    const int c = c0 + tx;
#pragma unroll
    for (int r = 0; r < 4; r++) {
        int pl = ty + 8 * r;
        if (c < C)
            tile[pl][tx] = sb[(size_t)(p0 + pl) * C + c];
    }
    __syncthreads();

    float cv = cnt[(size_t)n * HW + p0 + tx];
    float inv = 1.f / ((cv == 0.f) ? 1.f : cv);
#pragma unroll
    for (int r = 0; r < 4; r++) {
        int cc = c0 + ty + 8 * r;
        if (cc < C)
            out[((size_t)n * C + cc) * HW + p0 + tx] = tile[tx][ty + 8 * r] * inv;
    }
}

// ---------------------------------------------------------------------------
// Host launcher — dual batch pipeline + side stream (graph-capturable).
// ---------------------------------------------------------------------------
extern "C" void kernel_launch(void* const* d_in, const int* in_sizes, int n_in,
                              void* d_out, int out_size) {
    const float* img  = (const float*)d_in[0];
    const float* flow = (const float*)d_in[1];
    float* out = (float*)d_out;

    static cudaStream_t s2 = nullptr, s3 = nullptr;
    static cudaEvent_t evFork, evJoin, evPre[4], evB0[4], evB1[4];
    if (!s2) {
        cudaStreamCreateWithFlags(&s2, cudaStreamNonBlocking);
        cudaStreamCreateWithFlags(&s3, cudaStreamNonBlocking);
        cudaEventCreateWithFlags(&evFork, cudaEventDisableTiming);
        cudaEventCreateWithFlags(&evJoin, cudaEventDisableTiming);
        for (int i = 0; i < 4; i++) {
            cudaEventCreateWithFlags(&evPre[i], cudaEventDisableTiming);
            cudaEventCreateWithFlags(&evB0[i], cudaEventDisableTiming);
            cudaEventCreateWithFlags(&evB1[i], cudaEventDisableTiming);
        }
    }

    float *fa, *fb, *scrA, *scrB, *cntA, *cntB, *flbuf;
    cudaGetSymbolAddress((void**)&fa,   g_fa);
    cudaGetSymbolAddress((void**)&fb,   g_fb);
    cudaGetSymbolAddress((void**)&scrA, g_scrA);
    cudaGetSymbolAddress((void**)&scrB, g_scrB);
    cudaGetSymbolAddress((void**)&cntA, g_cntA);
    cudaGetSymbolAddress((void**)&cntB, g_cntB);
    cudaGetSymbolAddress((void**)&flbuf, g_fl);

    const int Cin[4]  = {3, 16, 32, 64};
    const int Cout[4] = {16, 32, 64, 128};
    const int Hin[4]  = {512, 256, 128, 64};

    size_t regOff[4];
    float* fl[4];
    {
        size_t a = 0, f = 0;
        for (int L = 0; L < 4; L++) {
            regOff[L] = a;
            int ho = Hin[L] / 2;
            a += (size_t)NB * Cout[L] * (ho + 2) * (ho + 2);
            fl[L] = flbuf + f;
            f += (size_t)NB * 2 * ho * ho;
        }
    }
    float* scrP[4] = {scrA, scrB, scrA, scrB};
    float* cntP[4] = {cntA, cntB, cntA, cntB};

    // ---- fork ----
    cudaEventRecord(evFork, 0);
    cudaStreamWaitEvent(s2, evFork, 0);
    cudaStreamWaitEvent(s3, evFork, 0);

    // ---- side stream: borders (merged), flow chain, first memsets ----
    {
        BorderJobs J{};
        int nj = 0;
        int maxtot = 0;
        for (int L = 0; L < 4; L++) {
            int ho = Hin[L] / 2;
            J.sel[nj] = 0; J.off[nj] = (long long)regOff[L];
            J.NC[nj] = NB * Cout[L]; J.H[nj] = ho;
            int tot = J.NC[nj] * (2 * (ho + 2) + 2 * ho);
            if (tot > maxtot) maxtot = tot;
            nj++;
            if (L < 3) {
                J.sel[nj] = 1; J.off[nj] = (long long)regOff[L];
                J.NC[nj] = NB * Cout[L]; J.H[nj] = ho;
                nj++;
            }
        }
        J.njobs = nj;
        dim3 grd((maxtot + 255) / 256, nj);
        zero_borders_all<<<grd, 256, 0, s2>>>(fa, fb, J);
    }

    {
        int ho0 = Hin[0] / 2;
        halve_flow_kernel<<<(NB * 2 * ho0 * ho0 + 255) / 256, 256, 0, s2>>>(
            flow, fl[0], ho0, ho0);
        cudaMemsetAsync(scrP[0], 0, (size_t)NB * Cout[0] * ho0 * ho0 * sizeof(float), s2);
        cudaMemsetAsync(cntP[0], 0, (size_t)NB * ho0 * ho0 * sizeof(float), s2);
        cudaEventRecord(evPre[0], s2);

        for (int L = 1; L < 4; L++) {
            int ho = Hin[L] / 2;
            halve_flow_kernel<<<(NB * 2 * ho * ho + 255) / 256, 256, 0, s2>>>(
                fl[L - 1], fl[L], ho, ho);
        }
        int ho1 = Hin[1] / 2;
        cudaMemsetAsync(scrP[1], 0, (size_t)NB * Cout[1] * ho1 * ho1 * sizeof(float), s2);
        cudaMemsetAsync(cntP[1], 0, (size_t)NB * ho1 * ho1 * sizeof(float), s2);
        cudaEventRecord(evPre[1], s2);
    }

    size_t off = 0;
    size_t outOff[4];
    for (int L = 0; L < 4; L++) { outOff[L] = off; off += (size_t)NB * Cout[L] * (Hin[L] / 2) * (Hin[L] / 2); }

    cudaStream_t hs[2] = {(cudaStream_t)0, s3};
    cudaEvent_t* evBh[2] = {evB0, evB1};

    for (int L = 0; L < 4; L++) {
        const int ci = Cin[L], co = Cout[L], hi = Hin[L], ho = hi / 2;
        const float* wA = (const float*)d_in[2 + 6 * L + 0];
        const float* bA = (const float*)d_in[2 + 6 * L + 1];
        const float* aA = (const float*)d_in[2 + 6 * L + 2];
        const float* wB = (const float*)d_in[2 + 6 * L + 3];
        const float* bB = (const float*)d_in[2 + 6 * L + 4];
        const float* aB = (const float*)d_in[2 + 6 * L + 5];

        const int po = ho + 2;
        const size_t planeO = (size_t)po * po;
        float* faL = fa + regOff[L] + po + 1;
        float* fbL = fb + regOff[L] + po + 1;

        for (int h = 0; h < 2; h++) {
            cudaStream_t st = hs[h];
            const int n0 = h * NBH;

            // --- conv_a: stride 2, 8co x 4rows ---
            {
                dim3 blk(32, 8);
                dim3 grd(ho / 32, ho / 32, NBH * (co / 8));
                size_t sm = 8 * ci * 9 * sizeof(float);
                if (L == 0) {
                    conv3x3_prelu<2, 4, 8, true, false, true, 2><<<grd, blk, sm, st>>>(
                        img, wA, bA, aA, faL, ci, co, hi, hi,
                        hi, (size_t)hi * hi, po, planeO, nullptr, nullptr, nullptr, n0);
                } else {
                    const int pi = hi + 2;
                    const float* inL = fb + regOff[L - 1] + pi + 1;
                    conv3x3_prelu<2, 4, 8, false, false, true, 2><<<grd, blk, sm, st>>>(
                        inL, wA, bA, aA, faL, ci, co, hi, hi,
                        pi, (size_t)pi * pi, po, planeO, nullptr, nullptr, nullptr, n0);
                }
            }

            cudaStreamWaitEvent(st, evPre[L], 0);

            // --- conv_b with fused splat; no fb write at L3 ---
            {
                dim3 blk(32, 8);
                size_t sm = 4 * co * 9 * sizeof(float);
                if (ho >= 64) {
                    dim3 grd(ho / 32, ho / 64, NBH * (co / 4));
                    conv3x3_prelu<1, 8, 4, false, true, true, 4><<<grd, blk, sm, st>>>(
                        faL, wB, bB, aB, fbL, co, co, ho, ho,
                        po, planeO, po, planeO, fl[L], scrP[L], cntP[L], n0);
                } else {
                    dim3 grd(ho / 32, ho / 32, NBH * (co / 4));
                    conv3x3_prelu<1, 4, 4, false, true, false, 4><<<grd, blk, sm, st>>>(
                        faL, wB, bB, aB, fbL, co, co, ho, ho,
                        po, planeO, po, planeO, fl[L], scrP[L], cntP[L], n0);
                }
            }
            cudaEventRecord(evBh[h][L], st);
        }

        // --- side stream: transpose this level after BOTH halves; memset L+2 ---
        cudaStreamWaitEvent(s2, evB0[L], 0);
        cudaStreamWaitEvent(s2, evB1[L], 0);
        {
            int HW = ho * ho;
            dim3 blk(32, 8);
            dim3 grd(HW / 32, (co + 31) / 32, NB);
            norm_transpose<<<grd, blk, 0, s2>>>(scrP[L], cntP[L], out + outOff[L], co, HW);
        }
        if (L + 2 < 4) {
            int ho2 = Hin[L + 2] / 2;
            cudaMemsetAsync(scrP[L + 2], 0,
                            (size_t)NB * Cout[L + 2] * ho2 * ho2 * sizeof(float), s2);
            cudaMemsetAsync(cntP[L + 2], 0,
                            (size_t)NB * ho2 * ho2 * sizeof(float), s2);
            cudaEventRecord(evPre[L + 2], s2);
        }
    }

    // ---- join ----
    cudaEventRecord(evJoin, s2);
    cudaStreamWaitEvent(0, evJoin, 0);
}